// round 2
// baseline (speedup 1.0000x reference)
#include <cuda_runtime.h>

typedef unsigned long long ull;

#define WP_STRIDE 68
#define G_STRIDE 116

// shared layout (float offsets)
#define OFF_WP 0            // 112*68 = 7616
#define OFF_G  7616         // 64*116 = 7424
#define OFF_BP 15040        // 116
#define OFF_BC 15156        // 64
#define OFF_Q  15220        // 8*16*68 = 8704
#define OFF_PR 23924        // 8*16*116 = 14848
#define OFF_RD 38772        // 8*64 = 512
#define SMEM_FLOATS 39284   // 157136 bytes

__device__ __align__(16) float g_G[64 * G_STRIDE];

static __device__ __forceinline__ ull pk(float x, float y) {
    ull r; asm("mov.b64 %0, {%1,%2};" : "=l"(r) : "f"(x), "f"(y)); return r;
}
static __device__ __forceinline__ float2 upk(ull v) {
    float2 r; asm("mov.b64 {%0,%1}, %2;" : "=f"(r.x), "=f"(r.y) : "l"(v)); return r;
}
static __device__ __forceinline__ ull fma2(ull a, ull b, ull c) {
    ull d; asm("fma.rn.f32x2 %0, %1, %2, %3;" : "=l"(d) : "l"(a), "l"(b), "l"(c)); return d;
}
static __device__ __forceinline__ float dot4(float4 a, float4 b) {
    float d = a.x * b.x; d = fmaf(a.y, b.y, d); d = fmaf(a.z, b.z, d); d = fmaf(a.w, b.w, d); return d;
}
static __device__ __forceinline__ float2 rx(float2 v, int m) {
    v.x += __shfl_xor_sync(0xffffffffu, v.x, m);
    v.y += __shfl_xor_sync(0xffffffffu, v.y, m);
    return v;
}
static __device__ __forceinline__ float4 rx4(float4 v, int m) {
    v.x += __shfl_xor_sync(0xffffffffu, v.x, m);
    v.y += __shfl_xor_sync(0xffffffffu, v.y, m);
    v.z += __shfl_xor_sync(0xffffffffu, v.z, m);
    v.w += __shfl_xor_sync(0xffffffffu, v.w, m);
    return v;
}

// G[n][m]: m<64: (Wc@Wu0)[n][m]; 64..95: Wc@Wu1; 96..111: Wc@Wu2;
// 112..114: Wc@bu_t; 115: 0
__global__ void build_G_kernel(const float* __restrict__ Wc,
                               const float* __restrict__ Wu0,
                               const float* __restrict__ Wu1,
                               const float* __restrict__ Wu2,
                               const float* __restrict__ bu0,
                               const float* __restrict__ bu1,
                               const float* __restrict__ bu2)
{
    int n = blockIdx.x, m = threadIdx.x;
    if (m >= G_STRIDE) return;
    const float* wcn = Wc + n * 64;
    float s = 0.0f;
    if (m < 64)       { for (int h = 0; h < 64; h++) s = fmaf(wcn[h], Wu0[h * 64 + m],      s); }
    else if (m < 96)  { for (int h = 0; h < 64; h++) s = fmaf(wcn[h], Wu1[h * 32 + (m-64)], s); }
    else if (m < 112) { for (int h = 0; h < 64; h++) s = fmaf(wcn[h], Wu2[h * 16 + (m-96)], s); }
    else if (m == 112){ for (int h = 0; h < 64; h++) s = fmaf(wcn[h], bu0[h], s); }
    else if (m == 113){ for (int h = 0; h < 64; h++) s = fmaf(wcn[h], bu1[h], s); }
    else if (m == 114){ for (int h = 0; h < 64; h++) s = fmaf(wcn[h], bu2[h], s); }
    g_G[n * G_STRIDE + m] = s;
}

__global__ void __launch_bounds__(256, 1)
retr_kernel(const float* __restrict__ q,
            const float* __restrict__ mem0,
            const float* __restrict__ mem1,
            const float* __restrict__ mem2,
            const float* __restrict__ Wp0,
            const float* __restrict__ Wp1,
            const float* __restrict__ Wp2,
            const float* __restrict__ bp0,
            const float* __restrict__ bp1,
            const float* __restrict__ bp2,
            const float* __restrict__ bc,
            float* __restrict__ out)
{
    extern __shared__ float sh[];
    const int tid = threadIdx.x, lane = tid & 31, warp = tid >> 5;

    // ---- block init ----
    #pragma unroll 1
    for (int i = tid; i < 112 * 16; i += 256) {
        int row = i >> 4, c4 = (i & 15) << 2;
        const float* src = (row < 64) ? (Wp0 + row * 64)
                         : (row < 96) ? (Wp1 + (row - 64) * 64)
                                      : (Wp2 + (row - 96) * 64);
        *(float4*)(sh + OFF_WP + row * WP_STRIDE + c4) = *(const float4*)(src + c4);
    }
    #pragma unroll 1
    for (int i = tid; i < (64 * G_STRIDE) / 4; i += 256)
        ((float4*)(sh + OFF_G))[i] = ((const float4*)g_G)[i];
    if (tid < 112)
        sh[OFF_BP + tid] = (tid < 64) ? bp0[tid] : (tid < 96) ? bp1[tid - 64] : bp2[tid - 96];
    if (tid < 64) sh[OFF_BC + tid] = bc[tid];
    __syncthreads();

    const int rowbase = blockIdx.x * 128 + warp * 16;
    float* sQw = sh + OFF_Q  + warp * 16 * WP_STRIDE;
    float* sPR = sh + OFF_PR + warp * 16 * G_STRIDE;
    float* sRd = sh + OFF_RD + warp * 64;

    // stage q tile
    {
        const float4* qg = (const float4*)(q + (size_t)rowbase * 64);
        #pragma unroll
        for (int i = 0; i < 8; i++) {
            int idx = lane + i * 32;
            *(float4*)(sQw + (idx >> 4) * WP_STRIDE + (idx & 15) * 4) = qg[idx];
        }
    }
    __syncwarp();

    // pre-issue stage2 row-0 mem loads (hide DRAM under stage1)
    const float* m0p = mem0 + (size_t)rowbase * 256 + 4 * lane;
    const float* m1p = mem1 + (size_t)rowbase * 256 + 4 * lane;
    const float* m2p = mem2 + (size_t)rowbase * 256 + 4 * lane;
    float4 n0a = *(const float4*)m0p, n0b = *(const float4*)(m0p + 128);
    float4 n1a = *(const float4*)m1p, n1b = *(const float4*)(m1p + 128);
    float4 n2a = *(const float4*)m2p, n2b = *(const float4*)(m2p + 128);

    // ---- stage 1: qp = q @ Wp^T + bp (two column passes) ----
    #pragma unroll 1
    for (int pass = 0; pass < 2; pass++) {
        int cA = pass ? lane + 64 : lane;
        int cB = pass ? 96 + (lane & 15) : lane + 32;
        bool wB = (pass == 0) || (lane < 16);
        ull accA[16], accB[16];
        #pragma unroll
        for (int r = 0; r < 16; r++) { accA[r] = 0ull; accB[r] = 0ull; }
        #pragma unroll 2
        for (int kq = 0; kq < 16; kq++) {
            float4 wa = *(const float4*)(sh + OFF_WP + cA * WP_STRIDE + kq * 4);
            float4 wb = *(const float4*)(sh + OFF_WP + cB * WP_STRIDE + kq * 4);
            ull wa01 = pk(wa.x, wa.y), wa23 = pk(wa.z, wa.w);
            ull wb01 = pk(wb.x, wb.y), wb23 = pk(wb.z, wb.w);
            #pragma unroll
            for (int r = 0; r < 16; r++) {
                float4 qv = *(const float4*)(sQw + r * WP_STRIDE + kq * 4);
                ull q01 = pk(qv.x, qv.y), q23 = pk(qv.z, qv.w);
                accA[r] = fma2(wa01, q01, accA[r]);
                accA[r] = fma2(wa23, q23, accA[r]);
                accB[r] = fma2(wb01, q01, accB[r]);
                accB[r] = fma2(wb23, q23, accB[r]);
            }
        }
        float ba = sh[OFF_BP + cA], bb = sh[OFF_BP + cB];
        #pragma unroll
        for (int r = 0; r < 16; r++) {
            float2 a = upk(accA[r]);
            sPR[r * G_STRIDE + cA] = a.x + a.y + ba;
            if (wB) { float2 b2 = upk(accB[r]); sPR[r * G_STRIDE + cB] = b2.x + b2.y + bb; }
        }
    }
    __syncwarp();

    // ---- stage 2: per-row sims/softmax/retrieval ----
    #pragma unroll 1
    for (int r = 0; r < 16; r++) {
        float4 v0a = n0a, v0b = n0b, v1a = n1a, v1b = n1b, v2a = n2a, v2b = n2b;
        if (r < 15) {
            const float* a0 = m0p + (r + 1) * 256;
            const float* a1 = m1p + (r + 1) * 256;
            const float* a2 = m2p + (r + 1) * 256;
            n0a = *(const float4*)a0; n0b = *(const float4*)(a0 + 128);
            n1a = *(const float4*)a1; n1b = *(const float4*)(a1 + 128);
            n2a = *(const float4*)a2; n2b = *(const float4*)(a2 + 128);
        }
        float* pr = sPR + r * G_STRIDE;
        float4 qp0 = *(const float4*)(pr + 4 * (lane & 15));
        float4 qp1 = *(const float4*)(pr + 64 + 4 * (lane & 7));
        float4 qp2 = *(const float4*)(pr + 96 + 4 * (lane & 3));
        float2 s0 = make_float2(dot4(v0a, qp0), dot4(v0b, qp0));
        float2 s1 = make_float2(dot4(v1a, qp1), dot4(v1b, qp1));
        float2 s2 = make_float2(dot4(v2a, qp2), dot4(v2b, qp2));
        s0 = rx(s0, 1); s0 = rx(s0, 2); s0 = rx(s0, 4); s0 = rx(s0, 8);
        s1 = rx(s1, 1); s1 = rx(s1, 2); s1 = rx(s1, 4);
        s2 = rx(s2, 1); s2 = rx(s2, 2);
        if (!(lane & 15)) { sRd[(lane >> 4)]      = s0.x; sRd[2  + (lane >> 4)] = s0.y; }
        if (!(lane & 7))  { sRd[4 + (lane >> 3)]  = s1.x; sRd[8  + (lane >> 3)] = s1.y; }
        if (!(lane & 3))  { sRd[12 + (lane >> 2)] = s2.x; sRd[20 + (lane >> 2)] = s2.y; }
        __syncwarp();
        if (lane < 28) {
            float sc = lane < 4 ? 0.125f : (lane < 12 ? 0.17677669529663689f : 0.25f);
            sRd[32 + lane] = __expf(sRd[lane] * sc);
        }
        __syncwarp();
        float4 e0  = *(const float4*)(sRd + 32);
        float4 e1a = *(const float4*)(sRd + 36), e1b = *(const float4*)(sRd + 40);
        float4 e2a = *(const float4*)(sRd + 44), e2b = *(const float4*)(sRd + 48);
        float4 e2c = *(const float4*)(sRd + 52), e2d = *(const float4*)(sRd + 56);
        float sum0 = e0.x + e0.y + e0.z + e0.w;
        float max0 = fmaxf(fmaxf(e0.x, e0.y), fmaxf(e0.z, e0.w));
        float sum1 = e1a.x + e1a.y + e1a.z + e1a.w + e1b.x + e1b.y + e1b.z + e1b.w;
        float max1 = fmaxf(fmaxf(fmaxf(e1a.x, e1a.y), fmaxf(e1a.z, e1a.w)),
                           fmaxf(fmaxf(e1b.x, e1b.y), fmaxf(e1b.z, e1b.w)));
        float sum2 = e2a.x + e2a.y + e2a.z + e2a.w + e2b.x + e2b.y + e2b.z + e2b.w
                   + e2c.x + e2c.y + e2c.z + e2c.w + e2d.x + e2d.y + e2d.z + e2d.w;
        float max2 = fmaxf(fmaxf(fmaxf(fmaxf(e2a.x, e2a.y), fmaxf(e2a.z, e2a.w)),
                                 fmaxf(fmaxf(e2b.x, e2b.y), fmaxf(e2b.z, e2b.w))),
                           fmaxf(fmaxf(fmaxf(e2c.x, e2c.y), fmaxf(e2c.z, e2c.w)),
                                 fmaxf(fmaxf(e2d.x, e2d.y), fmaxf(e2d.z, e2d.w))));
        float i0 = __fdividef(1.0f, sum0), i1 = __fdividef(1.0f, sum1), i2 = __fdividef(1.0f, sum2);
        float ec0 = __expf(max0 * i0), ec1 = __expf(max1 * i1), ec2 = __expf(max2 * i2);
        float ci = __fdividef(1.0f, ec0 + ec1 + ec2);
        float c0 = ec0 * ci, c1 = ec1 * ci, c2 = ec2 * ci;
        float k0 = c0 * i0, k1 = c1 * i1, k2 = c2 * i2;
        float w0a = k0 * ((lane & 16) ? e0.y : e0.x);
        float w0b = k0 * ((lane & 16) ? e0.w : e0.z);
        float w1a = k1 * sRd[36 + (lane >> 3)];
        float w1b = k1 * sRd[40 + (lane >> 3)];
        float w2a = k2 * sRd[44 + (lane >> 2)];
        float w2b = k2 * sRd[52 + (lane >> 2)];

        float4 r0 = make_float4(w0a * v0a.x + w0b * v0b.x, w0a * v0a.y + w0b * v0b.y,
                                w0a * v0a.z + w0b * v0b.z, w0a * v0a.w + w0b * v0b.w);
        r0 = rx4(r0, 16);
        if (lane < 16) *(float4*)(pr + 4 * lane) = r0;
        float4 r1 = make_float4(w1a * v1a.x + w1b * v1b.x, w1a * v1a.y + w1b * v1b.y,
                                w1a * v1a.z + w1b * v1b.z, w1a * v1a.w + w1b * v1b.w);
        r1 = rx4(r1, 8); r1 = rx4(r1, 16);
        if (lane < 8) *(float4*)(pr + 64 + 4 * lane) = r1;
        float4 r2 = make_float4(w2a * v2a.x + w2b * v2b.x, w2a * v2a.y + w2b * v2b.y,
                                w2a * v2a.z + w2b * v2b.z, w2a * v2a.w + w2b * v2b.w);
        r2 = rx4(r2, 4); r2 = rx4(r2, 8); r2 = rx4(r2, 16);
        if (lane < 4) *(float4*)(pr + 96 + 4 * lane) = r2;
        if (lane == 0) *(float4*)(pr + 112) = make_float4(c0, c1, c2, 0.0f);
        __syncwarp();
    }

    // ---- stage 3: out = r @ G^T + bc ----
    {
        int nA = lane, nB = lane + 32;
        ull accA[16], accB[16];
        #pragma unroll
        for (int r = 0; r < 16; r++) { accA[r] = 0ull; accB[r] = 0ull; }
        const float* gA = sh + OFF_G + nA * G_STRIDE;
        const float* gB = sh + OFF_G + nB * G_STRIDE;
        #pragma unroll 2
        for (int jq = 0; jq < 29; jq++) {
            float4 ga = *(const float4*)(gA + jq * 4);
            float4 gb = *(const float4*)(gB + jq * 4);
            ull ga01 = pk(ga.x, ga.y), ga23 = pk(ga.z, ga.w);
            ull gb01 = pk(gb.x, gb.y), gb23 = pk(gb.z, gb.w);
            #pragma unroll
            for (int r = 0; r < 16; r++) {
                float4 rv = *(const float4*)(sPR + r * G_STRIDE + jq * 4);
                ull r01 = pk(rv.x, rv.y), r23 = pk(rv.z, rv.w);
                accA[r] = fma2(ga01, r01, accA[r]);
                accA[r] = fma2(ga23, r23, accA[r]);
                accB[r] = fma2(gb01, r01, accB[r]);
                accB[r] = fma2(gb23, r23, accB[r]);
            }
        }
        float bA = sh[OFF_BC + nA], bB = sh[OFF_BC + nB];
        #pragma unroll
        for (int r = 0; r < 16; r++) {
            float2 a = upk(accA[r]);
            float2 b = upk(accB[r]);
            size_t o = (size_t)(rowbase + r) * 64;
            out[o + nA] = a.x + a.y + bA;
            out[o + nB] = b.x + b.y + bB;
        }
    }
}

extern "C" void kernel_launch(void* const* d_in, const int* in_sizes, int n_in,
                              void* d_out, int out_size)
{
    (void)n_in; (void)out_size;
    const float* q    = (const float*)d_in[0];
    const float* mem0 = (const float*)d_in[1];
    const float* mem1 = (const float*)d_in[2];
    const float* mem2 = (const float*)d_in[3];
    const float *Wp0, *bp0, *Wp1, *bp1, *Wp2, *bp2;
    const float *Wu0, *bu0, *Wu1, *bu1, *Wu2, *bu2;
    if (in_sizes[6] == 64 * 64) {
        // dict insertion order: Wp0,bp0,Wu0,bu0, Wp1,bp1,Wu1,bu1, Wp2,bp2,Wu2,bu2
        Wp0 = (const float*)d_in[4];  bp0 = (const float*)d_in[5];
        Wu0 = (const float*)d_in[6];  bu0 = (const float*)d_in[7];
        Wp1 = (const float*)d_in[8];  bp1 = (const float*)d_in[9];
        Wu1 = (const float*)d_in[10]; bu1 = (const float*)d_in[11];
        Wp2 = (const float*)d_in[12]; bp2 = (const float*)d_in[13];
        Wu2 = (const float*)d_in[14]; bu2 = (const float*)d_in[15];
    } else {
        // signature order: Wp0,bp0,Wp1,bp1,Wp2,bp2, Wu0,bu0,Wu1,bu1,Wu2,bu2
        Wp0 = (const float*)d_in[4];  bp0 = (const float*)d_in[5];
        Wp1 = (const float*)d_in[6];  bp1 = (const float*)d_in[7];
        Wp2 = (const float*)d_in[8];  bp2 = (const float*)d_in[9];
        Wu0 = (const float*)d_in[10]; bu0 = (const float*)d_in[11];
        Wu1 = (const float*)d_in[12]; bu1 = (const float*)d_in[13];
        Wu2 = (const float*)d_in[14]; bu2 = (const float*)d_in[15];
    }
    const float* Wc = (const float*)d_in[16];
    const float* bc = (const float*)d_in[17];
    int B = in_sizes[0] / 64;

    build_G_kernel<<<64, 128>>>(Wc, Wu0, Wu1, Wu2, bu0, bu1, bu2);

    cudaFuncSetAttribute(retr_kernel, cudaFuncAttributeMaxDynamicSharedMemorySize,
                         SMEM_FLOATS * sizeof(float));
    retr_kernel<<<B / 128, 256, SMEM_FLOATS * sizeof(float)>>>(
        q, mem0, mem1, mem2, Wp0, Wp1, Wp2, bp0, bp1, bp2, bc, (float*)d_out);
}

// round 3
// speedup vs baseline: 1.2489x; 1.2489x over previous
#include <cuda_runtime.h>

typedef unsigned long long ull;

#define WP_STRIDE 68
#define G_STRIDE 116
#define NWARP 16
#define ROWS 8

// shared layout (float offsets)
#define OFF_WP 0            // 112*68 = 7616
#define OFF_G  7616         // 64*116 = 7424
#define OFF_BP 15040        // 116
#define OFF_BC 15156        // 64
#define OFF_Q  15220        // 16*8*68 = 8704
#define OFF_PR 23924        // 16*8*116 = 14848
#define OFF_RD 38772        // 16*64 = 1024
#define SMEM_FLOATS 39796   // 159184 bytes

__device__ __align__(16) float g_G[64 * G_STRIDE];

static __device__ __forceinline__ ull pk(float x, float y) {
    ull r; asm("mov.b64 %0, {%1,%2};" : "=l"(r) : "f"(x), "f"(y)); return r;
}
static __device__ __forceinline__ float2 upk(ull v) {
    float2 r; asm("mov.b64 {%0,%1}, %2;" : "=f"(r.x), "=f"(r.y) : "l"(v)); return r;
}
static __device__ __forceinline__ ull fma2(ull a, ull b, ull c) {
    ull d; asm("fma.rn.f32x2 %0, %1, %2, %3;" : "=l"(d) : "l"(a), "l"(b), "l"(c)); return d;
}
static __device__ __forceinline__ float dot4(float4 a, float4 b) {
    float d = a.x * b.x; d = fmaf(a.y, b.y, d); d = fmaf(a.z, b.z, d); d = fmaf(a.w, b.w, d); return d;
}
static __device__ __forceinline__ float2 rx(float2 v, int m) {
    v.x += __shfl_xor_sync(0xffffffffu, v.x, m);
    v.y += __shfl_xor_sync(0xffffffffu, v.y, m);
    return v;
}
static __device__ __forceinline__ float4 rx4(float4 v, int m) {
    v.x += __shfl_xor_sync(0xffffffffu, v.x, m);
    v.y += __shfl_xor_sync(0xffffffffu, v.y, m);
    v.z += __shfl_xor_sync(0xffffffffu, v.z, m);
    v.w += __shfl_xor_sync(0xffffffffu, v.w, m);
    return v;
}

// G[n][m]: m<64: (Wc@Wu0)[n][m]; 64..95: Wc@Wu1; 96..111: Wc@Wu2;
// 112..114: Wc@bu_t; 115: 0
__global__ void build_G_kernel(const float* __restrict__ Wc,
                               const float* __restrict__ Wu0,
                               const float* __restrict__ Wu1,
                               const float* __restrict__ Wu2,
                               const float* __restrict__ bu0,
                               const float* __restrict__ bu1,
                               const float* __restrict__ bu2)
{
    int n = blockIdx.x, m = threadIdx.x;
    if (m >= G_STRIDE) return;
    const float* wcn = Wc + n * 64;
    float s = 0.0f;
    if (m < 64)       { for (int h = 0; h < 64; h++) s = fmaf(wcn[h], Wu0[h * 64 + m],      s); }
    else if (m < 96)  { for (int h = 0; h < 64; h++) s = fmaf(wcn[h], Wu1[h * 32 + (m-64)], s); }
    else if (m < 112) { for (int h = 0; h < 64; h++) s = fmaf(wcn[h], Wu2[h * 16 + (m-96)], s); }
    else if (m == 112){ for (int h = 0; h < 64; h++) s = fmaf(wcn[h], bu0[h], s); }
    else if (m == 113){ for (int h = 0; h < 64; h++) s = fmaf(wcn[h], bu1[h], s); }
    else if (m == 114){ for (int h = 0; h < 64; h++) s = fmaf(wcn[h], bu2[h], s); }
    g_G[n * G_STRIDE + m] = s;
}

__global__ void __launch_bounds__(512, 1)
retr_kernel(const float* __restrict__ q,
            const float* __restrict__ mem0,
            const float* __restrict__ mem1,
            const float* __restrict__ mem2,
            const float* __restrict__ Wp0,
            const float* __restrict__ Wp1,
            const float* __restrict__ Wp2,
            const float* __restrict__ bp0,
            const float* __restrict__ bp1,
            const float* __restrict__ bp2,
            const float* __restrict__ bc,
            float* __restrict__ out)
{
    extern __shared__ float sh[];
    const int tid = threadIdx.x, lane = tid & 31, warp = tid >> 5;

    // ---- block init ----
    #pragma unroll 1
    for (int i = tid; i < 112 * 16; i += 512) {
        int row = i >> 4, c4 = (i & 15) << 2;
        const float* src = (row < 64) ? (Wp0 + row * 64)
                         : (row < 96) ? (Wp1 + (row - 64) * 64)
                                      : (Wp2 + (row - 96) * 64);
        *(float4*)(sh + OFF_WP + row * WP_STRIDE + c4) = *(const float4*)(src + c4);
    }
    #pragma unroll 1
    for (int i = tid; i < (64 * G_STRIDE) / 4; i += 512)
        ((float4*)(sh + OFF_G))[i] = ((const float4*)g_G)[i];
    if (tid < 112)
        sh[OFF_BP + tid] = (tid < 64) ? bp0[tid] : (tid < 96) ? bp1[tid - 64] : bp2[tid - 96];
    if (tid < 64) sh[OFF_BC + tid] = bc[tid];
    __syncthreads();

    const int rowbase = blockIdx.x * 128 + warp * ROWS;
    float* sQw = sh + OFF_Q  + warp * ROWS * WP_STRIDE;
    float* sPR = sh + OFF_PR + warp * ROWS * G_STRIDE;
    float* sRd = sh + OFF_RD + warp * 64;

    // stage q tile: 8 rows * 64 floats = 128 float4
    {
        const float4* qg = (const float4*)(q + (size_t)rowbase * 64);
        #pragma unroll
        for (int i = 0; i < 4; i++) {
            int idx = lane + i * 32;
            *(float4*)(sQw + (idx >> 4) * WP_STRIDE + (idx & 15) * 4) = qg[idx];
        }
    }
    __syncwarp();

    // pre-issue stage2 row-0 mem loads (hide DRAM under stage1)
    const float* m0p = mem0 + (size_t)rowbase * 256 + 4 * lane;
    const float* m1p = mem1 + (size_t)rowbase * 256 + 4 * lane;
    const float* m2p = mem2 + (size_t)rowbase * 256 + 4 * lane;
    float4 n0a = *(const float4*)m0p, n0b = *(const float4*)(m0p + 128);
    float4 n1a = *(const float4*)m1p, n1b = *(const float4*)(m1p + 128);
    float4 n2a = *(const float4*)m2p, n2b = *(const float4*)(m2p + 128);

    // ---- stage 1: qp = q @ Wp^T + bp (two column passes) ----
    #pragma unroll 1
    for (int pass = 0; pass < 2; pass++) {
        int cA = pass ? lane + 64 : lane;
        int cB = pass ? 96 + (lane & 15) : lane + 32;
        bool wB = (pass == 0) || (lane < 16);
        ull accA[ROWS], accB[ROWS];
        #pragma unroll
        for (int r = 0; r < ROWS; r++) { accA[r] = 0ull; accB[r] = 0ull; }
        #pragma unroll 2
        for (int kq = 0; kq < 16; kq++) {
            float4 wa = *(const float4*)(sh + OFF_WP + cA * WP_STRIDE + kq * 4);
            float4 wb = *(const float4*)(sh + OFF_WP + cB * WP_STRIDE + kq * 4);
            ull wa01 = pk(wa.x, wa.y), wa23 = pk(wa.z, wa.w);
            ull wb01 = pk(wb.x, wb.y), wb23 = pk(wb.z, wb.w);
            #pragma unroll
            for (int r = 0; r < ROWS; r++) {
                float4 qv = *(const float4*)(sQw + r * WP_STRIDE + kq * 4);
                ull q01 = pk(qv.x, qv.y), q23 = pk(qv.z, qv.w);
                accA[r] = fma2(wa01, q01, accA[r]);
                accA[r] = fma2(wa23, q23, accA[r]);
                accB[r] = fma2(wb01, q01, accB[r]);
                accB[r] = fma2(wb23, q23, accB[r]);
            }
        }
        float ba = sh[OFF_BP + cA], bb = sh[OFF_BP + cB];
        #pragma unroll
        for (int r = 0; r < ROWS; r++) {
            float2 a = upk(accA[r]);
            sPR[r * G_STRIDE + cA] = a.x + a.y + ba;
            if (wB) { float2 b2 = upk(accB[r]); sPR[r * G_STRIDE + cB] = b2.x + b2.y + bb; }
        }
    }
    __syncwarp();

    // ---- stage 2: per-row sims/softmax/retrieval ----
    #pragma unroll 1
    for (int r = 0; r < ROWS; r++) {
        float4 v0a = n0a, v0b = n0b, v1a = n1a, v1b = n1b, v2a = n2a, v2b = n2b;
        if (r < ROWS - 1) {
            const float* a0 = m0p + (r + 1) * 256;
            const float* a1 = m1p + (r + 1) * 256;
            const float* a2 = m2p + (r + 1) * 256;
            n0a = *(const float4*)a0; n0b = *(const float4*)(a0 + 128);
            n1a = *(const float4*)a1; n1b = *(const float4*)(a1 + 128);
            n2a = *(const float4*)a2; n2b = *(const float4*)(a2 + 128);
        }
        float* pr = sPR + r * G_STRIDE;
        float4 qp0 = *(const float4*)(pr + 4 * (lane & 15));
        float4 qp1 = *(const float4*)(pr + 64 + 4 * (lane & 7));
        float4 qp2 = *(const float4*)(pr + 96 + 4 * (lane & 3));
        float2 s0 = make_float2(dot4(v0a, qp0), dot4(v0b, qp0));
        float2 s1 = make_float2(dot4(v1a, qp1), dot4(v1b, qp1));
        float2 s2 = make_float2(dot4(v2a, qp2), dot4(v2b, qp2));
        s0 = rx(s0, 1); s0 = rx(s0, 2); s0 = rx(s0, 4); s0 = rx(s0, 8);
        s1 = rx(s1, 1); s1 = rx(s1, 2); s1 = rx(s1, 4);
        s2 = rx(s2, 1); s2 = rx(s2, 2);
        if (!(lane & 15)) { sRd[(lane >> 4)]      = s0.x; sRd[2  + (lane >> 4)] = s0.y; }
        if (!(lane & 7))  { sRd[4 + (lane >> 3)]  = s1.x; sRd[8  + (lane >> 3)] = s1.y; }
        if (!(lane & 3))  { sRd[12 + (lane >> 2)] = s2.x; sRd[20 + (lane >> 2)] = s2.y; }
        __syncwarp();
        if (lane < 28) {
            float sc = lane < 4 ? 0.125f : (lane < 12 ? 0.17677669529663689f : 0.25f);
            sRd[32 + lane] = __expf(sRd[lane] * sc);
        }
        __syncwarp();
        float4 e0  = *(const float4*)(sRd + 32);
        float4 e1a = *(const float4*)(sRd + 36), e1b = *(const float4*)(sRd + 40);
        float4 e2a = *(const float4*)(sRd + 44), e2b = *(const float4*)(sRd + 48);
        float4 e2c = *(const float4*)(sRd + 52), e2d = *(const float4*)(sRd + 56);
        float sum0 = e0.x + e0.y + e0.z + e0.w;
        float max0 = fmaxf(fmaxf(e0.x, e0.y), fmaxf(e0.z, e0.w));
        float sum1 = e1a.x + e1a.y + e1a.z + e1a.w + e1b.x + e1b.y + e1b.z + e1b.w;
        float max1 = fmaxf(fmaxf(fmaxf(e1a.x, e1a.y), fmaxf(e1a.z, e1a.w)),
                           fmaxf(fmaxf(e1b.x, e1b.y), fmaxf(e1b.z, e1b.w)));
        float sum2 = e2a.x + e2a.y + e2a.z + e2a.w + e2b.x + e2b.y + e2b.z + e2b.w
                   + e2c.x + e2c.y + e2c.z + e2c.w + e2d.x + e2d.y + e2d.z + e2d.w;
        float max2 = fmaxf(fmaxf(fmaxf(fmaxf(e2a.x, e2a.y), fmaxf(e2a.z, e2a.w)),
                                 fmaxf(fmaxf(e2b.x, e2b.y), fmaxf(e2b.z, e2b.w))),
                           fmaxf(fmaxf(fmaxf(e2c.x, e2c.y), fmaxf(e2c.z, e2c.w)),
                                 fmaxf(fmaxf(e2d.x, e2d.y), fmaxf(e2d.z, e2d.w))));
        float i0 = __fdividef(1.0f, sum0), i1 = __fdividef(1.0f, sum1), i2 = __fdividef(1.0f, sum2);
        float ec0 = __expf(max0 * i0), ec1 = __expf(max1 * i1), ec2 = __expf(max2 * i2);
        float ci = __fdividef(1.0f, ec0 + ec1 + ec2);
        float c0 = ec0 * ci, c1 = ec1 * ci, c2 = ec2 * ci;
        float k0 = c0 * i0, k1 = c1 * i1, k2 = c2 * i2;
        float w0a = k0 * ((lane & 16) ? e0.y : e0.x);
        float w0b = k0 * ((lane & 16) ? e0.w : e0.z);
        float w1a = k1 * sRd[36 + (lane >> 3)];
        float w1b = k1 * sRd[40 + (lane >> 3)];
        float w2a = k2 * sRd[44 + (lane >> 2)];
        float w2b = k2 * sRd[52 + (lane >> 2)];

        float4 r0 = make_float4(w0a * v0a.x + w0b * v0b.x, w0a * v0a.y + w0b * v0b.y,
                                w0a * v0a.z + w0b * v0b.z, w0a * v0a.w + w0b * v0b.w);
        r0 = rx4(r0, 16);
        if (lane < 16) *(float4*)(pr + 4 * lane) = r0;
        float4 r1 = make_float4(w1a * v1a.x + w1b * v1b.x, w1a * v1a.y + w1b * v1b.y,
                                w1a * v1a.z + w1b * v1b.z, w1a * v1a.w + w1b * v1b.w);
        r1 = rx4(r1, 8); r1 = rx4(r1, 16);
        if (lane < 8) *(float4*)(pr + 64 + 4 * lane) = r1;
        float4 r2 = make_float4(w2a * v2a.x + w2b * v2b.x, w2a * v2a.y + w2b * v2b.y,
                                w2a * v2a.z + w2b * v2b.z, w2a * v2a.w + w2b * v2b.w);
        r2 = rx4(r2, 4); r2 = rx4(r2, 8); r2 = rx4(r2, 16);
        if (lane < 4) *(float4*)(pr + 96 + 4 * lane) = r2;
        if (lane == 0) *(float4*)(pr + 112) = make_float4(c0, c1, c2, 0.0f);
        __syncwarp();
    }

    // ---- stage 3: out = r @ G^T + bc ----
    {
        int nA = lane, nB = lane + 32;
        ull accA[ROWS], accB[ROWS];
        #pragma unroll
        for (int r = 0; r < ROWS; r++) { accA[r] = 0ull; accB[r] = 0ull; }
        const float* gA = sh + OFF_G + nA * G_STRIDE;
        const float* gB = sh + OFF_G + nB * G_STRIDE;
        #pragma unroll 2
        for (int jq = 0; jq < 29; jq++) {
            float4 ga = *(const float4*)(gA + jq * 4);
            float4 gb = *(const float4*)(gB + jq * 4);
            ull ga01 = pk(ga.x, ga.y), ga23 = pk(ga.z, ga.w);
            ull gb01 = pk(gb.x, gb.y), gb23 = pk(gb.z, gb.w);
            #pragma unroll
            for (int r = 0; r < ROWS; r++) {
                float4 rv = *(const float4*)(sPR + r * G_STRIDE + jq * 4);
                ull r01 = pk(rv.x, rv.y), r23 = pk(rv.z, rv.w);
                accA[r] = fma2(ga01, r01, accA[r]);
                accA[r] = fma2(ga23, r23, accA[r]);
                accB[r] = fma2(gb01, r01, accB[r]);
                accB[r] = fma2(gb23, r23, accB[r]);
            }
        }
        float bA = sh[OFF_BC + nA], bB = sh[OFF_BC + nB];
        #pragma unroll
        for (int r = 0; r < ROWS; r++) {
            float2 a = upk(accA[r]);
            float2 b = upk(accB[r]);
            size_t o = (size_t)(rowbase + r) * 64;
            out[o + nA] = a.x + a.y + bA;
            out[o + nB] = b.x + b.y + bB;
        }
    }
}

extern "C" void kernel_launch(void* const* d_in, const int* in_sizes, int n_in,
                              void* d_out, int out_size)
{
    (void)n_in; (void)out_size;
    const float* q    = (const float*)d_in[0];
    const float* mem0 = (const float*)d_in[1];
    const float* mem1 = (const float*)d_in[2];
    const float* mem2 = (const float*)d_in[3];
    const float *Wp0, *bp0, *Wp1, *bp1, *Wp2, *bp2;
    const float *Wu0, *bu0, *Wu1, *bu1, *Wu2, *bu2;
    if (in_sizes[6] == 64 * 64) {
        // dict insertion order: Wp0,bp0,Wu0,bu0, Wp1,bp1,Wu1,bu1, Wp2,bp2,Wu2,bu2
        Wp0 = (const float*)d_in[4];  bp0 = (const float*)d_in[5];
        Wu0 = (const float*)d_in[6];  bu0 = (const float*)d_in[7];
        Wp1 = (const float*)d_in[8];  bp1 = (const float*)d_in[9];
        Wu1 = (const float*)d_in[10]; bu1 = (const float*)d_in[11];
        Wp2 = (const float*)d_in[12]; bp2 = (const float*)d_in[13];
        Wu2 = (const float*)d_in[14]; bu2 = (const float*)d_in[15];
    } else {
        // signature order: Wp0,bp0,Wp1,bp1,Wp2,bp2, Wu0,bu0,Wu1,bu1,Wu2,bu2
        Wp0 = (const float*)d_in[4];  bp0 = (const float*)d_in[5];
        Wp1 = (const float*)d_in[6];  bp1 = (const float*)d_in[7];
        Wp2 = (const float*)d_in[8];  bp2 = (const float*)d_in[9];
        Wu0 = (const float*)d_in[10]; bu0 = (const float*)d_in[11];
        Wu1 = (const float*)d_in[12]; bu1 = (const float*)d_in[13];
        Wu2 = (const float*)d_in[14]; bu2 = (const float*)d_in[15];
    }
    const float* Wc = (const float*)d_in[16];
    const float* bc = (const float*)d_in[17];
    int B = in_sizes[0] / 64;

    build_G_kernel<<<64, 128>>>(Wc, Wu0, Wu1, Wu2, bu0, bu1, bu2);

    cudaFuncSetAttribute(retr_kernel, cudaFuncAttributeMaxDynamicSharedMemorySize,
                         SMEM_FLOATS * sizeof(float));
    retr_kernel<<<B / 128, 512, SMEM_FLOATS * sizeof(float)>>>(
        q, mem0, mem1, mem2, Wp0, Wp1, Wp2, bp0, bp1, bp2, bc, (float*)d_out);
}

// round 7
// speedup vs baseline: 1.2570x; 1.0065x over previous
#include <cuda_runtime.h>

typedef unsigned long long ull;

#define WP_STRIDE 68
#define G_STRIDE 116
#define ROWS 8

// shared layout (float offsets)
#define OFF_WP 0            // 112*68 = 7616
#define OFF_G  7616         // 64*116 = 7424
#define OFF_BP 15040        // 116
#define OFF_BC 15156        // 64
#define OFF_Q  15220        // 16*8*68 = 8704
#define OFF_PR 23924        // 16*8*116 = 14848
#define SMEM_FLOATS 38772   // 155088 bytes

__device__ __align__(16) float g_G[64 * G_STRIDE];

static __device__ __forceinline__ float2 upk(ull v) {
    float2 r; asm("mov.b64 {%0,%1}, %2;" : "=f"(r.x), "=f"(r.y) : "l"(v)); return r;
}
static __device__ __forceinline__ ull fma2(ull a, ull b, ull c) {
    ull d; asm("fma.rn.f32x2 %0, %1, %2, %3;" : "=l"(d) : "l"(a), "l"(b), "l"(c)); return d;
}
static __device__ __forceinline__ float dot4(float4 a, float4 b) {
    float d = a.x * b.x; d = fmaf(a.y, b.y, d); d = fmaf(a.z, b.z, d); d = fmaf(a.w, b.w, d); return d;
}
static __device__ __forceinline__ float2 rx(float2 v, int m) {
    v.x += __shfl_xor_sync(0xffffffffu, v.x, m);
    v.y += __shfl_xor_sync(0xffffffffu, v.y, m);
    return v;
}
static __device__ __forceinline__ float4 rx4(float4 v, int m) {
    v.x += __shfl_xor_sync(0xffffffffu, v.x, m);
    v.y += __shfl_xor_sync(0xffffffffu, v.y, m);
    v.z += __shfl_xor_sync(0xffffffffu, v.z, m);
    v.w += __shfl_xor_sync(0xffffffffu, v.w, m);
    return v;
}
static __device__ __forceinline__ float rsum(float v, int m) {
    return v + __shfl_xor_sync(0xffffffffu, v, m);
}
static __device__ __forceinline__ float rmax(float v, int m) {
    return fmaxf(v, __shfl_xor_sync(0xffffffffu, v, m));
}

// G[n][m]: m<64: (Wc@Wu0)[n][m]; 64..95: Wc@Wu1; 96..111: Wc@Wu2;
// 112..114: Wc@bu_t; 115: 0
__global__ void build_G_kernel(const float* __restrict__ Wc,
                               const float* __restrict__ Wu0,
                               const float* __restrict__ Wu1,
                               const float* __restrict__ Wu2,
                               const float* __restrict__ bu0,
                               const float* __restrict__ bu1,
                               const float* __restrict__ bu2)
{
    int n = blockIdx.x, m = threadIdx.x;
    if (m >= G_STRIDE) return;
    const float* wcn = Wc + n * 64;
    float s = 0.0f;
    if (m < 64)       { for (int h = 0; h < 64; h++) s = fmaf(wcn[h], Wu0[h * 64 + m],      s); }
    else if (m < 96)  { for (int h = 0; h < 64; h++) s = fmaf(wcn[h], Wu1[h * 32 + (m-64)], s); }
    else if (m < 112) { for (int h = 0; h < 64; h++) s = fmaf(wcn[h], Wu2[h * 16 + (m-96)], s); }
    else if (m == 112){ for (int h = 0; h < 64; h++) s = fmaf(wcn[h], bu0[h], s); }
    else if (m == 113){ for (int h = 0; h < 64; h++) s = fmaf(wcn[h], bu1[h], s); }
    else if (m == 114){ for (int h = 0; h < 64; h++) s = fmaf(wcn[h], bu2[h], s); }
    g_G[n * G_STRIDE + m] = s;
}

__global__ void __launch_bounds__(512, 1)
retr_kernel(const float* __restrict__ q,
            const float* __restrict__ mem0,
            const float* __restrict__ mem1,
            const float* __restrict__ mem2,
            const float* __restrict__ Wp0,
            const float* __restrict__ Wp1,
            const float* __restrict__ Wp2,
            const float* __restrict__ bp0,
            const float* __restrict__ bp1,
            const float* __restrict__ bp2,
            const float* __restrict__ bc,
            float* __restrict__ out)
{
    extern __shared__ float sh[];
    const int tid = threadIdx.x, lane = tid & 31, warp = tid >> 5;

    // ---- block init ----
    #pragma unroll 1
    for (int i = tid; i < 112 * 16; i += 512) {
        int row = i >> 4, c4 = (i & 15) << 2;
        const float* src = (row < 64) ? (Wp0 + row * 64)
                         : (row < 96) ? (Wp1 + (row - 64) * 64)
                                      : (Wp2 + (row - 96) * 64);
        *(float4*)(sh + OFF_WP + row * WP_STRIDE + c4) = *(const float4*)(src + c4);
    }
    #pragma unroll 1
    for (int i = tid; i < (64 * G_STRIDE) / 4; i += 512)
        ((float4*)(sh + OFF_G))[i] = ((const float4*)g_G)[i];
    if (tid < 112)
        sh[OFF_BP + tid] = (tid < 64) ? bp0[tid] : (tid < 96) ? bp1[tid - 64] : bp2[tid - 96];
    if (tid < 64) sh[OFF_BC + tid] = bc[tid];
    __syncthreads();

    const int rowbase = blockIdx.x * 128 + warp * ROWS;
    float* sQw = sh + OFF_Q  + warp * ROWS * WP_STRIDE;
    float* sPR = sh + OFF_PR + warp * ROWS * G_STRIDE;

    // stage q tile: 8 rows * 64 floats = 128 float4
    {
        const float4* qg = (const float4*)(q + (size_t)rowbase * 64);
        #pragma unroll
        for (int i = 0; i < 4; i++) {
            int idx = lane + i * 32;
            *(float4*)(sQw + (idx >> 4) * WP_STRIDE + (idx & 15) * 4) = qg[idx];
        }
    }
    __syncwarp();

    // pre-issue stage2 row-0 mem loads (hide DRAM under stage1)
    const float* m0p = mem0 + (size_t)rowbase * 256 + 4 * lane;
    const float* m1p = mem1 + (size_t)rowbase * 256 + 4 * lane;
    const float* m2p = mem2 + (size_t)rowbase * 256 + 4 * lane;
    float4 n0a = *(const float4*)m0p, n0b = *(const float4*)(m0p + 128);
    float4 n1a = *(const float4*)m1p, n1b = *(const float4*)(m1p + 128);
    float4 n2a = *(const float4*)m2p, n2b = *(const float4*)(m2p + 128);

    // ---- stage 1: qp = q @ Wp^T + bp (two column passes) ----
    #pragma unroll 1
    for (int pass = 0; pass < 2; pass++) {
        int cA = pass ? lane + 64 : lane;
        int cB = pass ? 96 + (lane & 15) : lane + 32;
        bool wB = (pass == 0) || (lane < 16);
        ull accA[ROWS], accB[ROWS];
        #pragma unroll
        for (int r = 0; r < ROWS; r++) { accA[r] = 0ull; accB[r] = 0ull; }
        #pragma unroll 4
        for (int kq = 0; kq < 16; kq++) {
            ulonglong2 wa = *(const ulonglong2*)(sh + OFF_WP + cA * WP_STRIDE + kq * 4);
            ulonglong2 wb = *(const ulonglong2*)(sh + OFF_WP + cB * WP_STRIDE + kq * 4);
            #pragma unroll
            for (int r = 0; r < ROWS; r++) {
                ulonglong2 qv = *(const ulonglong2*)(sQw + r * WP_STRIDE + kq * 4);
                accA[r] = fma2(wa.x, qv.x, accA[r]);
                accA[r] = fma2(wa.y, qv.y, accA[r]);
                accB[r] = fma2(wb.x, qv.x, accB[r]);
                accB[r] = fma2(wb.y, qv.y, accB[r]);
            }
        }
        float ba = sh[OFF_BP + cA], bb = sh[OFF_BP + cB];
        #pragma unroll
        for (int r = 0; r < ROWS; r++) {
            float2 a = upk(accA[r]);
            sPR[r * G_STRIDE + cA] = a.x + a.y + ba;
            if (wB) { float2 b2 = upk(accB[r]); sPR[r * G_STRIDE + cB] = b2.x + b2.y + bb; }
        }
    }
    __syncwarp();

    // ---- stage 2: per-row sims/softmax/retrieval (all-register softmax) ----
    #pragma unroll 1
    for (int r = 0; r < ROWS; r++) {
        float4 v0a = n0a, v0b = n0b, v1a = n1a, v1b = n1b, v2a = n2a, v2b = n2b;
        if (r < ROWS - 1) {
            const float* a0 = m0p + (r + 1) * 256;
            const float* a1 = m1p + (r + 1) * 256;
            const float* a2 = m2p + (r + 1) * 256;
            n0a = *(const float4*)a0; n0b = *(const float4*)(a0 + 128);
            n1a = *(const float4*)a1; n1b = *(const float4*)(a1 + 128);
            n2a = *(const float4*)a2; n2b = *(const float4*)(a2 + 128);
        }
        float* pr = sPR + r * G_STRIDE;
        float4 qp0 = *(const float4*)(pr + 4 * (lane & 15));
        float4 qp1 = *(const float4*)(pr + 64 + 4 * (lane & 7));
        float4 qp2 = *(const float4*)(pr + 96 + 4 * (lane & 3));
        float2 s0 = make_float2(dot4(v0a, qp0), dot4(v0b, qp0));
        float2 s1 = make_float2(dot4(v1a, qp1), dot4(v1b, qp1));
        float2 s2 = make_float2(dot4(v2a, qp2), dot4(v2b, qp2));
        s0 = rx(s0, 1); s0 = rx(s0, 2); s0 = rx(s0, 4); s0 = rx(s0, 8);
        s1 = rx(s1, 1); s1 = rx(s1, 2); s1 = rx(s1, 4);
        s2 = rx(s2, 1); s2 = rx(s2, 2);
        // per-lane exps of own slots
        float e0x = __expf(s0.x * 0.125f),               e0y = __expf(s0.y * 0.125f);
        float e1x = __expf(s1.x * 0.17677669529663689f), e1y = __expf(s1.y * 0.17677669529663689f);
        float e2x = __expf(s2.x * 0.25f),                e2y = __expf(s2.y * 0.25f);
        // sums & maxes via scalar butterflies
        float p0 = e0x + e0y, m0 = fmaxf(e0x, e0y);
        float p1 = e1x + e1y, m1 = fmaxf(e1x, e1y);
        float p2 = e2x + e2y, m2 = fmaxf(e2x, e2y);
        p0 = rsum(p0, 16);                                   m0 = rmax(m0, 16);
        p1 = rsum(p1, 8);  p1 = rsum(p1, 16);                m1 = rmax(m1, 8);  m1 = rmax(m1, 16);
        p2 = rsum(p2, 4);  p2 = rsum(p2, 8); p2 = rsum(p2, 16);
        m2 = rmax(m2, 4);  m2 = rmax(m2, 8); m2 = rmax(m2, 16);
        float i0 = __fdividef(1.0f, p0), i1 = __fdividef(1.0f, p1), i2 = __fdividef(1.0f, p2);
        float ec0 = __expf(m0 * i0), ec1 = __expf(m1 * i1), ec2 = __expf(m2 * i2);
        float ci = __fdividef(1.0f, ec0 + ec1 + ec2);
        float c0 = ec0 * ci, c1 = ec1 * ci, c2 = ec2 * ci;
        float k0 = c0 * i0, k1 = c1 * i1, k2 = c2 * i2;
        float w0a = k0 * e0x, w0b = k0 * e0y;
        float w1a = k1 * e1x, w1b = k1 * e1y;
        float w2a = k2 * e2x, w2b = k2 * e2y;

        float4 r0 = make_float4(w0a * v0a.x + w0b * v0b.x, w0a * v0a.y + w0b * v0b.y,
                                w0a * v0a.z + w0b * v0b.z, w0a * v0a.w + w0b * v0b.w);
        r0 = rx4(r0, 16);
        if (lane < 16) *(float4*)(pr + 4 * lane) = r0;
        float4 r1 = make_float4(w1a * v1a.x + w1b * v1b.x, w1a * v1a.y + w1b * v1b.y,
                                w1a * v1a.z + w1b * v1b.z, w1a * v1a.w + w1b * v1b.w);
        r1 = rx4(r1, 8); r1 = rx4(r1, 16);
        if (lane < 8) *(float4*)(pr + 64 + 4 * lane) = r1;
        float4 r2 = make_float4(w2a * v2a.x + w2b * v2b.x, w2a * v2a.y + w2b * v2b.y,
                                w2a * v2a.z + w2b * v2b.z, w2a * v2a.w + w2b * v2b.w);
        r2 = rx4(r2, 4); r2 = rx4(r2, 8); r2 = rx4(r2, 16);
        if (lane < 4) *(float4*)(pr + 96 + 4 * lane) = r2;
        if (lane == 0) *(float4*)(pr + 112) = make_float4(c0, c1, c2, 0.0f);
    }
    __syncwarp();

    // ---- stage 3: out = r @ G^T + bc ----
    {
        int nA = lane, nB = lane + 32;
        ull accA[ROWS], accB[ROWS];
        #pragma unroll
        for (int r = 0; r < ROWS; r++) { accA[r] = 0ull; accB[r] = 0ull; }
        const float* gA = sh + OFF_G + nA * G_STRIDE;
        const float* gB = sh + OFF_G + nB * G_STRIDE;
        #pragma unroll 2
        for (int jq = 0; jq < 29; jq++) {
            ulonglong2 ga = *(const ulonglong2*)(gA + jq * 4);
            ulonglong2 gb = *(const ulonglong2*)(gB + jq * 4);
            #pragma unroll
            for (int r = 0; r < ROWS; r++) {
                ulonglong2 rv = *(const ulonglong2*)(sPR + r * G_STRIDE + jq * 4);
                accA[r] = fma2(ga.x, rv.x, accA[r]);
                accA[r] = fma2(ga.y, rv.y, accA[r]);
                accB[r] = fma2(gb.x, rv.x, accB[r]);
                accB[r] = fma2(gb.y, rv.y, accB[r]);
            }
        }
        float bA = sh[OFF_BC + nA], bB = sh[OFF_BC + nB];
        #pragma unroll
        for (int r = 0; r < ROWS; r++) {
            float2 a = upk(accA[r]);
            float2 b = upk(accB[r]);
            size_t o = (size_t)(rowbase + r) * 64;
            out[o + nA] = a.x + a.y + bA;
            out[o + nB] = b.x + b.y + bB;
        }
    }
}

extern "C" void kernel_launch(void* const* d_in, const int* in_sizes, int n_in,
                              void* d_out, int out_size)
{
    (void)n_in; (void)out_size;
    const float* q    = (const float*)d_in[0];
    const float* mem0 = (const float*)d_in[1];
    const float* mem1 = (const float*)d_in[2];
    const float* mem2 = (const float*)d_in[3];
    const float *Wp0, *bp0, *Wp1, *bp1, *Wp2, *bp2;
    const float *Wu0, *bu0, *Wu1, *bu1, *Wu2, *bu2;
    if (in_sizes[6] == 64 * 64) {
        // dict insertion order: Wp0,bp0,Wu0,bu0, Wp1,bp1,Wu1,bu1, Wp2,bp2,Wu2,bu2
        Wp0 = (const float*)d_in[4];  bp0 = (const float*)d_in[5];
        Wu0 = (const float*)d_in[6];  bu0 = (const float*)d_in[7];
        Wp1 = (const float*)d_in[8];  bp1 = (const float*)d_in[9];
        Wu1 = (const float*)d_in[10]; bu1 = (const float*)d_in[11];
        Wp2 = (const float*)d_in[12]; bp2 = (const float*)d_in[13];
        Wu2 = (const float*)d_in[14]; bu2 = (const float*)d_in[15];
    } else {
        // signature order: Wp0,bp0,Wp1,bp1,Wp2,bp2, Wu0,bu0,Wu1,bu1,Wu2,bu2
        Wp0 = (const float*)d_in[4];  bp0 = (const float*)d_in[5];
        Wp1 = (const float*)d_in[6];  bp1 = (const float*)d_in[7];
        Wp2 = (const float*)d_in[8];  bp2 = (const float*)d_in[9];
        Wu0 = (const float*)d_in[10]; bu0 = (const float*)d_in[11];
        Wu1 = (const float*)d_in[12]; bu1 = (const float*)d_in[13];
        Wu2 = (const float*)d_in[14]; bu2 = (const float*)d_in[15];
    }
    const float* Wc = (const float*)d_in[16];
    const float* bc = (const float*)d_in[17];
    int B = in_sizes[0] / 64;

    build_G_kernel<<<64, 128>>>(Wc, Wu0, Wu1, Wu2, bu0, bu1, bu2);

    cudaFuncSetAttribute(retr_kernel, cudaFuncAttributeMaxDynamicSharedMemorySize,
                         SMEM_FLOATS * sizeof(float));
    retr_kernel<<<B / 128, 512, SMEM_FLOATS * sizeof(float)>>>(
        q, mem0, mem1, mem2, Wp0, Wp1, Wp2, bp0, bp1, bp2, bc, (float*)d_out);
}

// round 8
// speedup vs baseline: 1.2587x; 1.0014x over previous
#include <cuda_runtime.h>

typedef unsigned long long ull;

#define WP_STRIDE 68
#define G_STRIDE 116
#define ROWS 8

// shared layout (float offsets)
#define OFF_WP 0            // 112*68 = 7616
#define OFF_G  7616         // 64*116 = 7424
#define OFF_BP 15040        // 116
#define OFF_BC 15156        // 64
#define OFF_Q  15220        // 16*8*68 = 8704
#define OFF_PR 23924        // 16*8*116 = 14848
#define SMEM_FLOATS 38772   // 155088 bytes

__device__ __align__(16) float g_G[64 * G_STRIDE];

static __device__ __forceinline__ float2 upk(ull v) {
    float2 r; asm("mov.b64 {%0,%1}, %2;" : "=f"(r.x), "=f"(r.y) : "l"(v)); return r;
}
static __device__ __forceinline__ ull fma2(ull a, ull b, ull c) {
    ull d; asm("fma.rn.f32x2 %0, %1, %2, %3;" : "=l"(d) : "l"(a), "l"(b), "l"(c)); return d;
}
static __device__ __forceinline__ float dot4(float4 a, float4 b) {
    float d = a.x * b.x; d = fmaf(a.y, b.y, d); d = fmaf(a.z, b.z, d); d = fmaf(a.w, b.w, d); return d;
}
static __device__ __forceinline__ float2 rx(float2 v, int m) {
    v.x += __shfl_xor_sync(0xffffffffu, v.x, m);
    v.y += __shfl_xor_sync(0xffffffffu, v.y, m);
    return v;
}
static __device__ __forceinline__ float4 rx4(float4 v, int m) {
    v.x += __shfl_xor_sync(0xffffffffu, v.x, m);
    v.y += __shfl_xor_sync(0xffffffffu, v.y, m);
    v.z += __shfl_xor_sync(0xffffffffu, v.z, m);
    v.w += __shfl_xor_sync(0xffffffffu, v.w, m);
    return v;
}
static __device__ __forceinline__ float rsum(float v, int m) {
    return v + __shfl_xor_sync(0xffffffffu, v, m);
}
static __device__ __forceinline__ float rmax(float v, int m) {
    return fmaxf(v, __shfl_xor_sync(0xffffffffu, v, m));
}

// G[n][m]: m<64: (Wc@Wu0)[n][m]; 64..95: Wc@Wu1; 96..111: Wc@Wu2;
// 112..114: Wc@bu_t; 115: 0
__global__ void build_G_kernel(const float* __restrict__ Wc,
                               const float* __restrict__ Wu0,
                               const float* __restrict__ Wu1,
                               const float* __restrict__ Wu2,
                               const float* __restrict__ bu0,
                               const float* __restrict__ bu1,
                               const float* __restrict__ bu2)
{
    int n = blockIdx.x, m = threadIdx.x;
    if (m >= G_STRIDE) return;
    const float* wcn = Wc + n * 64;
    float s = 0.0f;
    if (m < 64)       { for (int h = 0; h < 64; h++) s = fmaf(wcn[h], Wu0[h * 64 + m],      s); }
    else if (m < 96)  { for (int h = 0; h < 64; h++) s = fmaf(wcn[h], Wu1[h * 32 + (m-64)], s); }
    else if (m < 112) { for (int h = 0; h < 64; h++) s = fmaf(wcn[h], Wu2[h * 16 + (m-96)], s); }
    else if (m == 112){ for (int h = 0; h < 64; h++) s = fmaf(wcn[h], bu0[h], s); }
    else if (m == 113){ for (int h = 0; h < 64; h++) s = fmaf(wcn[h], bu1[h], s); }
    else if (m == 114){ for (int h = 0; h < 64; h++) s = fmaf(wcn[h], bu2[h], s); }
    g_G[n * G_STRIDE + m] = s;
}

__global__ void __launch_bounds__(512, 1)
retr_kernel(const float* __restrict__ q,
            const float* __restrict__ mem0,
            const float* __restrict__ mem1,
            const float* __restrict__ mem2,
            const float* __restrict__ Wp0,
            const float* __restrict__ Wp1,
            const float* __restrict__ Wp2,
            const float* __restrict__ bp0,
            const float* __restrict__ bp1,
            const float* __restrict__ bp2,
            const float* __restrict__ bc,
            float* __restrict__ out)
{
    extern __shared__ float sh[];
    const int tid = threadIdx.x, lane = tid & 31, warp = tid >> 5;

    // ---- block init ----
    #pragma unroll 1
    for (int i = tid; i < 112 * 16; i += 512) {
        int row = i >> 4, c4 = (i & 15) << 2;
        const float* src = (row < 64) ? (Wp0 + row * 64)
                         : (row < 96) ? (Wp1 + (row - 64) * 64)
                                      : (Wp2 + (row - 96) * 64);
        *(float4*)(sh + OFF_WP + row * WP_STRIDE + c4) = *(const float4*)(src + c4);
    }
    #pragma unroll 1
    for (int i = tid; i < (64 * G_STRIDE) / 4; i += 512)
        ((float4*)(sh + OFF_G))[i] = ((const float4*)g_G)[i];
    if (tid < 112)
        sh[OFF_BP + tid] = (tid < 64) ? bp0[tid] : (tid < 96) ? bp1[tid - 64] : bp2[tid - 96];
    if (tid < 64) sh[OFF_BC + tid] = bc[tid];
    __syncthreads();

    const int rowbase = blockIdx.x * 128 + warp * ROWS;
    float* sQw = sh + OFF_Q  + warp * ROWS * WP_STRIDE;
    float* sPR = sh + OFF_PR + warp * ROWS * G_STRIDE;

    // stage q tile: 8 rows * 64 floats = 128 float4
    {
        const float4* qg = (const float4*)(q + (size_t)rowbase * 64);
        #pragma unroll
        for (int i = 0; i < 4; i++) {
            int idx = lane + i * 32;
            *(float4*)(sQw + (idx >> 4) * WP_STRIDE + (idx & 15) * 4) = qg[idx];
        }
    }
    __syncwarp();

    // pre-issue stage2 row-0 mem loads (hide DRAM under stage1)
    const float* m0p = mem0 + (size_t)rowbase * 256 + 4 * lane;
    const float* m1p = mem1 + (size_t)rowbase * 256 + 4 * lane;
    const float* m2p = mem2 + (size_t)rowbase * 256 + 4 * lane;
    float4 n0a = *(const float4*)m0p, n0b = *(const float4*)(m0p + 128);
    float4 n1a = *(const float4*)m1p, n1b = *(const float4*)(m1p + 128);
    float4 n2a = *(const float4*)m2p, n2b = *(const float4*)(m2p + 128);

    // ---- stage 1: qp = q @ Wp^T + bp (two column passes) ----
    #pragma unroll 1
    for (int pass = 0; pass < 2; pass++) {
        int cA = pass ? lane + 64 : lane;
        int cB = pass ? 96 + (lane & 15) : lane + 32;
        bool wB = (pass == 0) || (lane < 16);
        ull accA[ROWS], accB[ROWS];
        #pragma unroll
        for (int r = 0; r < ROWS; r++) { accA[r] = 0ull; accB[r] = 0ull; }
        #pragma unroll 4
        for (int kq = 0; kq < 16; kq++) {
            ulonglong2 wa = *(const ulonglong2*)(sh + OFF_WP + cA * WP_STRIDE + kq * 4);
            ulonglong2 wb = *(const ulonglong2*)(sh + OFF_WP + cB * WP_STRIDE + kq * 4);
            #pragma unroll
            for (int r = 0; r < ROWS; r++) {
                ulonglong2 qv = *(const ulonglong2*)(sQw + r * WP_STRIDE + kq * 4);
                accA[r] = fma2(wa.x, qv.x, accA[r]);
                accA[r] = fma2(wa.y, qv.y, accA[r]);
                accB[r] = fma2(wb.x, qv.x, accB[r]);
                accB[r] = fma2(wb.y, qv.y, accB[r]);
            }
        }
        float ba = sh[OFF_BP + cA], bb = sh[OFF_BP + cB];
        #pragma unroll
        for (int r = 0; r < ROWS; r++) {
            float2 a = upk(accA[r]);
            sPR[r * G_STRIDE + cA] = a.x + a.y + ba;
            if (wB) { float2 b2 = upk(accB[r]); sPR[r * G_STRIDE + cB] = b2.x + b2.y + bb; }
        }
    }
    __syncwarp();

    // ---- stage 2: per-row sims/softmax/retrieval (all-register softmax) ----
    #pragma unroll 1
    for (int r = 0; r < ROWS; r++) {
        float4 v0a = n0a, v0b = n0b, v1a = n1a, v1b = n1b, v2a = n2a, v2b = n2b;
        if (r < ROWS - 1) {
            const float* a0 = m0p + (r + 1) * 256;
            const float* a1 = m1p + (r + 1) * 256;
            const float* a2 = m2p + (r + 1) * 256;
            n0a = *(const float4*)a0; n0b = *(const float4*)(a0 + 128);
            n1a = *(const float4*)a1; n1b = *(const float4*)(a1 + 128);
            n2a = *(const float4*)a2; n2b = *(const float4*)(a2 + 128);
        }
        float* pr = sPR + r * G_STRIDE;
        float4 qp0 = *(const float4*)(pr + 4 * (lane & 15));
        float4 qp1 = *(const float4*)(pr + 64 + 4 * (lane & 7));
        float4 qp2 = *(const float4*)(pr + 96 + 4 * (lane & 3));
        float2 s0 = make_float2(dot4(v0a, qp0), dot4(v0b, qp0));
        float2 s1 = make_float2(dot4(v1a, qp1), dot4(v1b, qp1));
        float2 s2 = make_float2(dot4(v2a, qp2), dot4(v2b, qp2));
        s0 = rx(s0, 1); s0 = rx(s0, 2); s0 = rx(s0, 4); s0 = rx(s0, 8);
        s1 = rx(s1, 1); s1 = rx(s1, 2); s1 = rx(s1, 4);
        s2 = rx(s2, 1); s2 = rx(s2, 2);
        // per-lane exps of own slots
        float e0x = __expf(s0.x * 0.125f),               e0y = __expf(s0.y * 0.125f);
        float e1x = __expf(s1.x * 0.17677669529663689f), e1y = __expf(s1.y * 0.17677669529663689f);
        float e2x = __expf(s2.x * 0.25f),                e2y = __expf(s2.y * 0.25f);
        // sums & maxes via scalar butterflies
        float p0 = e0x + e0y, m0 = fmaxf(e0x, e0y);
        float p1 = e1x + e1y, m1 = fmaxf(e1x, e1y);
        float p2 = e2x + e2y, m2 = fmaxf(e2x, e2y);
        p0 = rsum(p0, 16);                                   m0 = rmax(m0, 16);
        p1 = rsum(p1, 8);  p1 = rsum(p1, 16);                m1 = rmax(m1, 8);  m1 = rmax(m1, 16);
        p2 = rsum(p2, 4);  p2 = rsum(p2, 8); p2 = rsum(p2, 16);
        m2 = rmax(m2, 4);  m2 = rmax(m2, 8); m2 = rmax(m2, 16);
        float i0 = __fdividef(1.0f, p0), i1 = __fdividef(1.0f, p1), i2 = __fdividef(1.0f, p2);
        float ec0 = __expf(m0 * i0), ec1 = __expf(m1 * i1), ec2 = __expf(m2 * i2);
        float ci = __fdividef(1.0f, ec0 + ec1 + ec2);
        float c0 = ec0 * ci, c1 = ec1 * ci, c2 = ec2 * ci;
        float k0 = c0 * i0, k1 = c1 * i1, k2 = c2 * i2;
        float w0a = k0 * e0x, w0b = k0 * e0y;
        float w1a = k1 * e1x, w1b = k1 * e1y;
        float w2a = k2 * e2x, w2b = k2 * e2y;

        float4 r0 = make_float4(w0a * v0a.x + w0b * v0b.x, w0a * v0a.y + w0b * v0b.y,
                                w0a * v0a.z + w0b * v0b.z, w0a * v0a.w + w0b * v0b.w);
        r0 = rx4(r0, 16);
        if (lane < 16) *(float4*)(pr + 4 * lane) = r0;
        float4 r1 = make_float4(w1a * v1a.x + w1b * v1b.x, w1a * v1a.y + w1b * v1b.y,
                                w1a * v1a.z + w1b * v1b.z, w1a * v1a.w + w1b * v1b.w);
        r1 = rx4(r1, 8); r1 = rx4(r1, 16);
        if (lane < 8) *(float4*)(pr + 64 + 4 * lane) = r1;
        float4 r2 = make_float4(w2a * v2a.x + w2b * v2b.x, w2a * v2a.y + w2b * v2b.y,
                                w2a * v2a.z + w2b * v2b.z, w2a * v2a.w + w2b * v2b.w);
        r2 = rx4(r2, 4); r2 = rx4(r2, 8); r2 = rx4(r2, 16);
        if (lane < 4) *(float4*)(pr + 96 + 4 * lane) = r2;
        if (lane == 0) *(float4*)(pr + 112) = make_float4(c0, c1, c2, 0.0f);
    }
    __syncwarp();

    // ---- stage 3: out = r @ G^T + bc ----
    {
        int nA = lane, nB = lane + 32;
        ull accA[ROWS], accB[ROWS];
        #pragma unroll
        for (int r = 0; r < ROWS; r++) { accA[r] = 0ull; accB[r] = 0ull; }
        const float* gA = sh + OFF_G + nA * G_STRIDE;
        const float* gB = sh + OFF_G + nB * G_STRIDE;
        #pragma unroll 2
        for (int jq = 0; jq < 29; jq++) {
            ulonglong2 ga = *(const ulonglong2*)(gA + jq * 4);
            ulonglong2 gb = *(const ulonglong2*)(gB + jq * 4);
            #pragma unroll
            for (int r = 0; r < ROWS; r++) {
                ulonglong2 rv = *(const ulonglong2*)(sPR + r * G_STRIDE + jq * 4);
                accA[r] = fma2(ga.x, rv.x, accA[r]);
                accA[r] = fma2(ga.y, rv.y, accA[r]);
                accB[r] = fma2(gb.x, rv.x, accB[r]);
                accB[r] = fma2(gb.y, rv.y, accB[r]);
            }
        }
        float bA = sh[OFF_BC + nA], bB = sh[OFF_BC + nB];
        #pragma unroll
        for (int r = 0; r < ROWS; r++) {
            float2 a = upk(accA[r]);
            float2 b = upk(accB[r]);
            size_t o = (size_t)(rowbase + r) * 64;
            out[o + nA] = a.x + a.y + bA;
            out[o + nB] = b.x + b.y + bB;
        }
    }
}

extern "C" void kernel_launch(void* const* d_in, const int* in_sizes, int n_in,
                              void* d_out, int out_size)
{
    (void)n_in; (void)out_size;
    const float* q    = (const float*)d_in[0];
    const float* mem0 = (const float*)d_in[1];
    const float* mem1 = (const float*)d_in[2];
    const float* mem2 = (const float*)d_in[3];
    const float *Wp0, *bp0, *Wp1, *bp1, *Wp2, *bp2;
    const float *Wu0, *bu0, *Wu1, *bu1, *Wu2, *bu2;
    if (in_sizes[6] == 64 * 64) {
        // dict insertion order: Wp0,bp0,Wu0,bu0, Wp1,bp1,Wu1,bu1, Wp2,bp2,Wu2,bu2
        Wp0 = (const float*)d_in[4];  bp0 = (const float*)d_in[5];
        Wu0 = (const float*)d_in[6];  bu0 = (const float*)d_in[7];
        Wp1 = (const float*)d_in[8];  bp1 = (const float*)d_in[9];
        Wu1 = (const float*)d_in[10]; bu1 = (const float*)d_in[11];
        Wp2 = (const float*)d_in[12]; bp2 = (const float*)d_in[13];
        Wu2 = (const float*)d_in[14]; bu2 = (const float*)d_in[15];
    } else {
        // signature order: Wp0,bp0,Wp1,bp1,Wp2,bp2, Wu0,bu0,Wu1,bu1,Wu2,bu2
        Wp0 = (const float*)d_in[4];  bp0 = (const float*)d_in[5];
        Wp1 = (const float*)d_in[6];  bp1 = (const float*)d_in[7];
        Wp2 = (const float*)d_in[8];  bp2 = (const float*)d_in[9];
        Wu0 = (const float*)d_in[10]; bu0 = (const float*)d_in[11];
        Wu1 = (const float*)d_in[12]; bu1 = (const float*)d_in[13];
        Wu2 = (const float*)d_in[14]; bu2 = (const float*)d_in[15];
    }
    const float* Wc = (const float*)d_in[16];
    const float* bc = (const float*)d_in[17];
    int B = in_sizes[0] / 64;

    build_G_kernel<<<64, 128>>>(Wc, Wu0, Wu1, Wu2, bu0, bu1, bu2);

    cudaFuncSetAttribute(retr_kernel, cudaFuncAttributeMaxDynamicSharedMemorySize,
                         SMEM_FLOATS * sizeof(float));
    retr_kernel<<<B / 128, 512, SMEM_FLOATS * sizeof(float)>>>(
        q, mem0, mem1, mem2, Wp0, Wp1, Wp2, bp0, bp1, bp2, bc, (float*)d_out);
}